// round 8
// baseline (speedup 1.0000x reference)
#include <cuda_runtime.h>

// Grid: 128^3 cells, cell = (bin+64), idx = x + 128*y + 16384*z
// Each cell: float4 {sum_x, sum_y, sum_z, count}
#define D    128
#define D3   (128*128*128)
#define OFF  64
#define NMAX 200704

__device__ float4 g_gridA[D3];     // scatter ping
__device__ float4 g_gridB[D3];     // scatter pong
__device__ float4 g_grid1[D3];     // conv output / gather source
__device__ float  g_Xbuf[2][NMAX * 3];
__device__ int    g_actA[16 * 128];   // activity flag per (ytile=y>>3, z)
__device__ int    g_actB[16 * 128];
__device__ unsigned g_maxd2_bits;
__device__ int g_done;

// ---------------------------------------------------------------- helpers
__device__ __forceinline__ int bin_of(float v) {
    // match jnp: (X / 0.1f).astype(int32) == IEEE RN divide, trunc toward zero
    int b = (int)__fdiv_rn(v, 0.1f);
    b += OFF;
    return min(max(b, 0), D - 1);
}

__device__ __forceinline__ void red4(float4* p, float x, float y, float z, float w) {
    asm volatile("red.global.add.v4.f32 [%0], {%1, %2, %3, %4};"
                 :: "l"(p), "f"(x), "f"(y), "f"(z), "f"(w) : "memory");
}

// ---------------------------------------------------------------- initial scatter (step 0 only)
__global__ void scatter0_kernel(const float* __restrict__ X, int n) {
    int i = blockIdx.x * blockDim.x + threadIdx.x;
    if (i >= n) return;
    float x = X[3 * i + 0];
    float y = X[3 * i + 1];
    float z = X[3 * i + 2];
    int yb = bin_of(y), zb = bin_of(z);
    int cell = bin_of(x) + (yb << 7) + (zb << 14);
    g_actA[((yb >> 3) << 7) + zb] = 1;
    red4(&g_gridA[cell], x, y, z, 1.0f);
}

// ---------------------------------------------------------------- fused 3D separable conv
// weights [1,2,3,2,1] per axis. Block: full x-line (128) x 8 output y-rows,
// z-seg of 8. 256 blocks x 1024 threads. Single smem stage: per slice each
// thread stores raw rows (r, r+8 if r<4), ONE sync, then computes its output
// row as a direct 5x5 (x,y) filter over raw. raw double-buffered so the next
// slice's stores need no extra sync. z handled by a 5-deep register ring,
// loop unrolled x5 so the ring rotates by register renaming (no MOVs).

struct ConvCtx {
    const float4* __restrict__ src;
    int x, r, y0, zlo, nsl;
    int ya1, ya2;                 // global y rows this thread loads
    int xm2, xm1, xp1, xp2;       // clamped x-neighbor columns
};

// one slice: store prefetched rows, sync, prefetch next, 5x5 filter -> acc
__device__ __forceinline__ float4 slice_body(float4 (*rb)[D], const ConvCtx& c,
                                             float4& pa, float4& pb, int zi) {
    rb[c.r][c.x] = pa;
    if (c.r < 4) rb[c.r + 8][c.x] = pb;
    __syncthreads();
    if (zi + 1 < c.nsl) {
        int zoff = (min(max(c.zlo - 2 + zi + 1, 0), D - 1)) << 14;
        pa = c.src[c.x + (c.ya1 << 7) + zoff];
        if (c.r < 4) pb = c.src[c.x + (c.ya2 << 7) + zoff];
    }
    const float WY[5] = {1.f, 2.f, 3.f, 2.f, 1.f};
    float4 acc = make_float4(0.f, 0.f, 0.f, 0.f);
#pragma unroll
    for (int j = 0; j < 5; j++) {
        const float4* rp = rb[c.r + j];
        float4 a = rp[c.xm2], b = rp[c.xm1], cc = rp[c.x], d = rp[c.xp1], e = rp[c.xp2];
        float w = WY[j];
        acc.x += w * ((a.x + e.x) + 2.f * (b.x + d.x) + 3.f * cc.x);
        acc.y += w * ((a.y + e.y) + 2.f * (b.y + d.y) + 3.f * cc.y);
        acc.z += w * ((a.z + e.z) + 2.f * (b.z + d.z) + 3.f * cc.z);
        acc.w += w * ((a.w + e.w) + 2.f * (b.w + d.w) + 3.f * cc.w);
    }
    return acc;
}

__device__ __forceinline__ void emit(const ConvCtx& c, int zi,
                                     float4 o0, float4 o1, float4 o2,
                                     float4 o3, float4 o4) {
    // o0 oldest .. o4 newest; z weights [1,2,3,2,1]
    int zo = c.zlo - 4 + zi;             // output slice for ring ending at zi
    float4 o;
    o.x = o0.x + 2.f * o1.x + 3.f * o2.x + 2.f * o3.x + o4.x;
    o.y = o0.y + 2.f * o1.y + 3.f * o2.y + 2.f * o3.y + o4.y;
    o.z = o0.z + 2.f * o1.z + 3.f * o2.z + 2.f * o3.z + o4.z;
    o.w = o0.w + 2.f * o1.w + 3.f * o2.w + 2.f * o3.w + o4.w;
    g_grid1[c.x + ((c.y0 + c.r) << 7) + (zo << 14)] = o;
}

__global__ __launch_bounds__(1024) void conv3d_kernel(int sel, int first) {
    __shared__ float4 raw[2][12][D];     // double-buffered, 48KB exactly

    if (blockIdx.x == 0 && threadIdx.x == 0) {
        // fold convergence check: uses previous step's max displacement^2
        if (first) g_done = 0;
        else if (__uint_as_float(g_maxd2_bits) <= 1e-6f) g_done = 1;
        g_maxd2_bits = 0u;
    }

    const float4* __restrict__ src = sel ? g_gridB : g_gridA;
    const int* __restrict__ act = sel ? g_actB : g_actA;

    ConvCtx c;
    c.src = src;
    c.x = threadIdx.x & 127;
    c.r = threadIdx.x >> 7;              // 0..7
    int yt = blockIdx.x & 15;            // 16 y-tiles of 8 rows
    int z0 = (blockIdx.x >> 4) << 3;     // 16 z-segments of 8 slices
    c.y0 = yt << 3;

    // per-warp activity ballot (no smem, no sync)
    {
        int lane = threadIdx.x & 31;
        int f = (lane < 8) ? act[(yt << 7) + z0 + lane] : 0;
        unsigned need = __ballot_sync(0xffffffffu, f != 0) & 0xffu;
        if (!need) return;
        c.zlo = z0 + __ffs(need) - 1;
        int zhi = z0 + 31 - __clz(need);
        c.nsl = zhi - c.zlo + 5;         // raw slices zlo-2 .. zhi+2
    }

    c.ya1 = min(max(c.y0 + c.r - 2, 0), D - 1);
    c.ya2 = min(max(c.y0 + c.r + 6, 0), D - 1);
    c.xm2 = max(c.x - 2, 0);
    c.xm1 = max(c.x - 1, 0);
    c.xp1 = min(c.x + 1, D - 1);
    c.xp2 = min(c.x + 2, D - 1);

    float4 pa, pb;
    {
        int zoff = (min(max(c.zlo - 2, 0), D - 1)) << 14;
        pa = src[c.x + (c.ya1 << 7) + zoff];
        if (c.r < 4) pb = src[c.x + (c.ya2 << 7) + zoff];
    }

    float4 q0, q1, q2, q3, q4;
    q0 = q1 = q2 = q3 = q4 = make_float4(0.f, 0.f, 0.f, 0.f);

    int zi = 0;
    while (true) {
        // k = 0
        q0 = slice_body(raw[zi & 1], c, pa, pb, zi);
        if (zi >= 4) emit(c, zi, q1, q2, q3, q4, q0);
        if (++zi >= c.nsl) break;
        // k = 1
        q1 = slice_body(raw[zi & 1], c, pa, pb, zi);
        if (zi >= 4) emit(c, zi, q2, q3, q4, q0, q1);
        if (++zi >= c.nsl) break;
        // k = 2
        q2 = slice_body(raw[zi & 1], c, pa, pb, zi);
        if (zi >= 4) emit(c, zi, q3, q4, q0, q1, q2);
        if (++zi >= c.nsl) break;
        // k = 3
        q3 = slice_body(raw[zi & 1], c, pa, pb, zi);
        if (zi >= 4) emit(c, zi, q4, q0, q1, q2, q3);
        if (++zi >= c.nsl) break;
        // k = 4
        q4 = slice_body(raw[zi & 1], c, pa, pb, zi);
        if (zi >= 4) emit(c, zi, q0, q1, q2, q3, q4);
        if (++zi >= c.nsl) break;
    }
}

// ---------------------------------------------------------------- fused gather + scatter(next)
// 1 point per thread (max warp-level parallelism).
__global__ void fused_gs_kernel(const float* __restrict__ Xext, int srcSel,
                                float* __restrict__ Oext, int dstSel,
                                int gsel, int doScatter, int n) {
    __shared__ float s_max[8];
    const float* X = (srcSel < 0) ? Xext : g_Xbuf[srcSel];
    float* Y = (dstSel < 0) ? Oext : g_Xbuf[dstSel];
    float4* gOld = gsel ? g_gridB : g_gridA;   // consumed this step -> zero
    float4* gNew = gsel ? g_gridA : g_gridB;   // next step's scatter target
    int* actOld = gsel ? g_actB : g_actA;
    int* actNew = gsel ? g_actA : g_actB;

    int i = blockIdx.x * blockDim.x + threadIdx.x;
    float d2 = 0.f;
    if (i < n) {
        float x = X[3 * i + 0];
        float y = X[3 * i + 1];
        float z = X[3 * i + 2];
        int yb = bin_of(y), zb = bin_of(z);
        int cell = bin_of(x) + (yb << 7) + (zb << 14);
        float4 t = g_grid1[cell];
        // undo this step's scatter: keeps grids & flags all-zero at boundaries
        gOld[cell] = make_float4(0.f, 0.f, 0.f, 0.f);
        actOld[((yb >> 3) << 7) + zb] = 0;
        float nx = __fdiv_rn(t.x, t.w);
        float ny = __fdiv_rn(t.y, t.w);
        float nz = __fdiv_rn(t.z, t.w);
        if (g_done) { nx = x; ny = y; nz = z; }
        Y[3 * i + 0] = nx;
        Y[3 * i + 1] = ny;
        Y[3 * i + 2] = nz;
        float dx = nx - x, dy = ny - y, dz = nz - z;
        d2 = dx * dx + dy * dy + dz * dz;
        if (doScatter) {
            int nyb = bin_of(ny), nzb = bin_of(nz);
            int ncell = bin_of(nx) + (nyb << 7) + (nzb << 14);
            actNew[((nyb >> 3) << 7) + nzb] = 1;
            red4(&gNew[ncell], nx, ny, nz, 1.0f);
        }
    }
#pragma unroll
    for (int o = 16; o > 0; o >>= 1)
        d2 = fmaxf(d2, __shfl_xor_sync(0xFFFFFFFFu, d2, o));
    int wid = threadIdx.x >> 5;
    if ((threadIdx.x & 31) == 0) s_max[wid] = d2;
    __syncthreads();
    if (threadIdx.x < 8) {
        float v = s_max[threadIdx.x];
#pragma unroll
        for (int o = 4; o > 0; o >>= 1)
            v = fmaxf(v, __shfl_xor_sync(0xFFu, v, o));
        if (threadIdx.x == 0)
            atomicMax(&g_maxd2_bits, __float_as_uint(v));
    }
}

// ---------------------------------------------------------------- launch
extern "C" void kernel_launch(void* const* d_in, const int* in_sizes, int n_in,
                              void* d_out, int out_size) {
    const float* Xin = (const float*)d_in[0];
    float* Out = (float*)d_out;
    int n = in_sizes[0] / 3;

    int pblocks = (n + 255) / 256;
    int srcSel[5] = {-1, 0, 1, 0, 1};
    int dstSel[5] = { 0, 1, 0, 1, -1};

    scatter0_kernel<<<pblocks, 256>>>(Xin, n);
    for (int s = 0; s < 5; s++) {
        int gsel = s & 1;
        conv3d_kernel<<<256, 1024>>>(gsel, s == 0);
        fused_gs_kernel<<<pblocks, 256>>>(Xin, srcSel[s], Out, dstSel[s],
                                          gsel, s < 4, n);
    }
}

// round 9
// speedup vs baseline: 1.1719x; 1.1719x over previous
#include <cuda_runtime.h>

// Grid: 128^3 cells, cell = (bin+64), idx = x + 128*y + 16384*z
// Each cell: float4 {sum_x, sum_y, sum_z, count}
#define D    128
#define D3   (128*128*128)
#define OFF  64
#define NMAX 200704

__device__ float4 g_gridA[D3];     // scatter ping
__device__ float4 g_gridB[D3];     // scatter pong
__device__ float4 g_grid1[D3];     // conv output / gather source
__device__ float  g_Xbuf[2][NMAX * 3];
__device__ int    g_actA[16 * 128];   // activity flag per (ytile=y>>3, z)
__device__ int    g_actB[16 * 128];
__device__ unsigned g_maxd2_bits;
__device__ int g_done;

// ---------------------------------------------------------------- helpers
__device__ __forceinline__ int bin_of(float v) {
    // match jnp: (X / 0.1f).astype(int32) == IEEE RN divide, trunc toward zero
    int b = (int)__fdiv_rn(v, 0.1f);
    b += OFF;
    return min(max(b, 0), D - 1);
}

__device__ __forceinline__ void red4(float4* p, float x, float y, float z, float w) {
    asm volatile("red.global.add.v4.f32 [%0], {%1, %2, %3, %4};"
                 :: "l"(p), "f"(x), "f"(y), "f"(z), "f"(w) : "memory");
}

__device__ __forceinline__ float4 shfl_up4(float4 v, int d) {
    float4 o;
    o.x = __shfl_up_sync(0xffffffffu, v.x, d);
    o.y = __shfl_up_sync(0xffffffffu, v.y, d);
    o.z = __shfl_up_sync(0xffffffffu, v.z, d);
    o.w = __shfl_up_sync(0xffffffffu, v.w, d);
    return o;
}
__device__ __forceinline__ float4 shfl_dn4(float4 v, int d) {
    float4 o;
    o.x = __shfl_down_sync(0xffffffffu, v.x, d);
    o.y = __shfl_down_sync(0xffffffffu, v.y, d);
    o.z = __shfl_down_sync(0xffffffffu, v.z, d);
    o.w = __shfl_down_sync(0xffffffffu, v.w, d);
    return o;
}

// x-filter [1,2,3,2,1] from register v; neighbors via shuffle; warp-boundary
// lanes use e1/e2 (preloaded from GLOBAL memory — no smem, no sync needed).
// lane 0:  vm1=e1, vm2=e2 | lane 1: vm2=e2 | lane 30: vp2=e2 | lane 31: vp1=e1, vp2=e2
__device__ __forceinline__ float4 xfilt(float4 v, float4 e1, float4 e2, int lane) {
    float4 vm1 = shfl_up4(v, 1);
    float4 vm2 = shfl_up4(v, 2);
    float4 vp1 = shfl_dn4(v, 1);
    float4 vp2 = shfl_dn4(v, 2);
    if (lane == 0)  vm1 = e1;
    if (lane < 2)   vm2 = e2;
    if (lane == 31) vp1 = e1;
    if (lane >= 30) vp2 = e2;
    float4 a;
    a.x = (vm2.x + vp2.x) + 2.f * (vm1.x + vp1.x) + 3.f * v.x;
    a.y = (vm2.y + vp2.y) + 2.f * (vm1.y + vp1.y) + 3.f * v.y;
    a.z = (vm2.z + vp2.z) + 2.f * (vm1.z + vp1.z) + 3.f * v.z;
    a.w = (vm2.w + vp2.w) + 2.f * (vm1.w + vp1.w) + 3.f * v.w;
    return a;
}

// ---------------------------------------------------------------- initial scatter (step 0 only)
__global__ void scatter0_kernel(const float* __restrict__ X, int n) {
    int i = blockIdx.x * blockDim.x + threadIdx.x;
    if (i >= n) return;
    float x = X[3 * i + 0];
    float y = X[3 * i + 1];
    float z = X[3 * i + 2];
    int yb = bin_of(y), zb = bin_of(z);
    int cell = bin_of(x) + (yb << 7) + (zb << 14);
    g_actA[((yb >> 3) << 7) + zb] = 1;
    red4(&g_gridA[cell], x, y, z, 1.0f);
}

// ---------------------------------------------------------------- fused 3D separable conv
// weights [1,2,3,2,1] per axis. Block: full x-line (128) x 8 output y-rows,
// z-seg of 8. 256 blocks x 1024 threads. x-filter fully in registers (warp
// shuffles; boundary lanes patched from GLOBAL loads) -> xf smem (double
// buffered) -> ONE sync -> y-filter. Smem ops/thread/slice: 6.5 vs 15.5 (R4).
// z via 5-deep register ring rotated by 5x loop unroll (no MOVs).

struct CCtx {
    const float4* __restrict__ src;
    int x, lane, r, y0, zlo, nsl;
    int ya1, ya2;                 // global y rows this thread loads
    int c1, c2;                   // boundary-lane extra global columns
    bool bnd;
};

__device__ __forceinline__ void load_slab(const CCtx& c, int zi,
                                          float4& pa, float4& pb,
                                          float4& e1a, float4& e2a,
                                          float4& e1b, float4& e2b) {
    int zoff = (min(max(c.zlo - 2 + zi, 0), D - 1)) << 14;
    const float4* rowa = c.src + (c.ya1 << 7) + zoff;
    pa = rowa[c.x];
    if (c.bnd) { e1a = rowa[c.c1]; e2a = rowa[c.c2]; }
    if (c.r < 4) {
        const float4* rowb = c.src + (c.ya2 << 7) + zoff;
        pb = rowb[c.x];
        if (c.bnd) { e1b = rowb[c.c1]; e2b = rowb[c.c2]; }
    }
}

// one slice: x-filter regs -> xf store -> prefetch next -> sync -> y-filter
__device__ __forceinline__ float4 slice_body(float4 (*xf)[D], const CCtx& c,
                                             float4& pa, float4& pb,
                                             float4& e1a, float4& e2a,
                                             float4& e1b, float4& e2b, int zi) {
    xf[c.r][c.x] = xfilt(pa, e1a, e2a, c.lane);
    if (c.r < 4) xf[c.r + 8][c.x] = xfilt(pb, e1b, e2b, c.lane);
    if (zi + 1 < c.nsl)
        load_slab(c, zi + 1, pa, pb, e1a, e2a, e1b, e2b);
    __syncthreads();
    float4 acc;
    float4 a0 = xf[c.r + 0][c.x];
    float4 a1 = xf[c.r + 1][c.x];
    float4 a2 = xf[c.r + 2][c.x];
    float4 a3 = xf[c.r + 3][c.x];
    float4 a4 = xf[c.r + 4][c.x];
    acc.x = (a0.x + a4.x) + 2.f * (a1.x + a3.x) + 3.f * a2.x;
    acc.y = (a0.y + a4.y) + 2.f * (a1.y + a3.y) + 3.f * a2.y;
    acc.z = (a0.z + a4.z) + 2.f * (a1.z + a3.z) + 3.f * a2.z;
    acc.w = (a0.w + a4.w) + 2.f * (a1.w + a3.w) + 3.f * a2.w;
    return acc;
}

__device__ __forceinline__ void emit(const CCtx& c, int zi,
                                     float4 o0, float4 o1, float4 o2,
                                     float4 o3, float4 o4) {
    int zo = c.zlo - 4 + zi;             // ring [zc-4..zc] centered at zc-2
    float4 o;
    o.x = (o0.x + o4.x) + 2.f * (o1.x + o3.x) + 3.f * o2.x;
    o.y = (o0.y + o4.y) + 2.f * (o1.y + o3.y) + 3.f * o2.y;
    o.z = (o0.z + o4.z) + 2.f * (o1.z + o3.z) + 3.f * o2.z;
    o.w = (o0.w + o4.w) + 2.f * (o1.w + o3.w) + 3.f * o2.w;
    g_grid1[c.x + ((c.y0 + c.r) << 7) + (zo << 14)] = o;
}

__global__ __launch_bounds__(1024) void conv3d_kernel(int sel, int first) {
    __shared__ float4 xf[2][12][D];      // double-buffered, 48KB exactly

    if (blockIdx.x == 0 && threadIdx.x == 0) {
        // fold convergence check: uses previous step's max displacement^2
        if (first) g_done = 0;
        else if (__uint_as_float(g_maxd2_bits) <= 1e-6f) g_done = 1;
        g_maxd2_bits = 0u;
    }

    const int* __restrict__ act = sel ? g_actB : g_actA;

    CCtx c;
    c.src = sel ? g_gridB : g_gridA;
    c.x = threadIdx.x & 127;
    c.lane = threadIdx.x & 31;
    c.r = threadIdx.x >> 7;              // 0..7
    int yt = blockIdx.x & 15;            // 16 y-tiles of 8 rows
    int z0 = (blockIdx.x >> 4) << 3;     // 16 z-segments of 8 slices
    c.y0 = yt << 3;

    // per-warp activity ballot (identical result in every warp)
    {
        int f = (c.lane < 8) ? act[(yt << 7) + z0 + c.lane] : 0;
        unsigned need = __ballot_sync(0xffffffffu, f != 0) & 0xffu;
        if (!need) return;
        c.zlo = z0 + __ffs(need) - 1;
        int zhi = z0 + 31 - __clz(need);
        c.nsl = zhi - c.zlo + 5;         // raw slices zlo-2 .. zhi+2
    }

    c.ya1 = min(max(c.y0 + c.r - 2, 0), D - 1);
    c.ya2 = min(max(c.y0 + c.r + 6, 0), D - 1);
    bool bLo = (c.lane < 2);
    c.bnd = bLo || (c.lane >= 30);
    c.c1 = bLo ? max(c.x - 1, 0) : min(c.x + 1, D - 1);
    c.c2 = bLo ? max(c.x - 2, 0) : min(c.x + 2, D - 1);

    float4 pa, pb, e1a, e2a, e1b, e2b;
    pa = pb = e1a = e2a = e1b = e2b = make_float4(0.f, 0.f, 0.f, 0.f);
    load_slab(c, 0, pa, pb, e1a, e2a, e1b, e2b);

    float4 q0, q1, q2, q3, q4;
    q0 = q1 = q2 = q3 = q4 = make_float4(0.f, 0.f, 0.f, 0.f);

    int zi = 0;
    while (true) {
        q0 = slice_body(xf[zi & 1], c, pa, pb, e1a, e2a, e1b, e2b, zi);
        if (zi >= 4) emit(c, zi, q1, q2, q3, q4, q0);
        if (++zi >= c.nsl) break;
        q1 = slice_body(xf[zi & 1], c, pa, pb, e1a, e2a, e1b, e2b, zi);
        if (zi >= 4) emit(c, zi, q2, q3, q4, q0, q1);
        if (++zi >= c.nsl) break;
        q2 = slice_body(xf[zi & 1], c, pa, pb, e1a, e2a, e1b, e2b, zi);
        if (zi >= 4) emit(c, zi, q3, q4, q0, q1, q2);
        if (++zi >= c.nsl) break;
        q3 = slice_body(xf[zi & 1], c, pa, pb, e1a, e2a, e1b, e2b, zi);
        if (zi >= 4) emit(c, zi, q4, q0, q1, q2, q3);
        if (++zi >= c.nsl) break;
        q4 = slice_body(xf[zi & 1], c, pa, pb, e1a, e2a, e1b, e2b, zi);
        if (zi >= 4) emit(c, zi, q0, q1, q2, q3, q4);
        if (++zi >= c.nsl) break;
    }
}

// ---------------------------------------------------------------- fused gather + scatter(next)
// 1 point per thread (max warp-level parallelism). Exact R4 version.
__global__ void fused_gs_kernel(const float* __restrict__ Xext, int srcSel,
                                float* __restrict__ Oext, int dstSel,
                                int gsel, int doScatter, int n) {
    __shared__ float s_max[8];
    const float* X = (srcSel < 0) ? Xext : g_Xbuf[srcSel];
    float* Y = (dstSel < 0) ? Oext : g_Xbuf[dstSel];
    float4* gOld = gsel ? g_gridB : g_gridA;   // consumed this step -> zero
    float4* gNew = gsel ? g_gridA : g_gridB;   // next step's scatter target
    int* actOld = gsel ? g_actB : g_actA;
    int* actNew = gsel ? g_actA : g_actB;

    int i = blockIdx.x * blockDim.x + threadIdx.x;
    float d2 = 0.f;
    if (i < n) {
        float x = X[3 * i + 0];
        float y = X[3 * i + 1];
        float z = X[3 * i + 2];
        int yb = bin_of(y), zb = bin_of(z);
        int cell = bin_of(x) + (yb << 7) + (zb << 14);
        float4 t = g_grid1[cell];
        // undo this step's scatter: keeps grids & flags all-zero at boundaries
        gOld[cell] = make_float4(0.f, 0.f, 0.f, 0.f);
        actOld[((yb >> 3) << 7) + zb] = 0;
        float nx = __fdiv_rn(t.x, t.w);
        float ny = __fdiv_rn(t.y, t.w);
        float nz = __fdiv_rn(t.z, t.w);
        if (g_done) { nx = x; ny = y; nz = z; }
        Y[3 * i + 0] = nx;
        Y[3 * i + 1] = ny;
        Y[3 * i + 2] = nz;
        float dx = nx - x, dy = ny - y, dz = nz - z;
        d2 = dx * dx + dy * dy + dz * dz;
        if (doScatter) {
            int nyb = bin_of(ny), nzb = bin_of(nz);
            int ncell = bin_of(nx) + (nyb << 7) + (nzb << 14);
            actNew[((nyb >> 3) << 7) + nzb] = 1;
            red4(&gNew[ncell], nx, ny, nz, 1.0f);
        }
    }
#pragma unroll
    for (int o = 16; o > 0; o >>= 1)
        d2 = fmaxf(d2, __shfl_xor_sync(0xFFFFFFFFu, d2, o));
    int wid = threadIdx.x >> 5;
    if ((threadIdx.x & 31) == 0) s_max[wid] = d2;
    __syncthreads();
    if (threadIdx.x < 8) {
        float v = s_max[threadIdx.x];
#pragma unroll
        for (int o = 4; o > 0; o >>= 1)
            v = fmaxf(v, __shfl_xor_sync(0xFFu, v, o));
        if (threadIdx.x == 0)
            atomicMax(&g_maxd2_bits, __float_as_uint(v));
    }
}

// ---------------------------------------------------------------- launch
extern "C" void kernel_launch(void* const* d_in, const int* in_sizes, int n_in,
                              void* d_out, int out_size) {
    const float* Xin = (const float*)d_in[0];
    float* Out = (float*)d_out;
    int n = in_sizes[0] / 3;

    int pblocks = (n + 255) / 256;
    int srcSel[5] = {-1, 0, 1, 0, 1};
    int dstSel[5] = { 0, 1, 0, 1, -1};

    scatter0_kernel<<<pblocks, 256>>>(Xin, n);
    for (int s = 0; s < 5; s++) {
        int gsel = s & 1;
        conv3d_kernel<<<256, 1024>>>(gsel, s == 0);
        fused_gs_kernel<<<pblocks, 256>>>(Xin, srcSel[s], Out, dstSel[s],
                                          gsel, s < 4, n);
    }
}